// round 13
// baseline (speedup 1.0000x reference)
#include <cuda_runtime.h>

#define BATCH 128
#define DIM   4096

// padded smem: float4-aligned, spreads strided groups across banks
__device__ __forceinline__ int phys(int i) {
    return i + 2 * (i >> 4) + 2 * (i >> 8);
}
#define BUF_F2 4640

// Scalar complex MAC with SPLIT accumulators (all FMAs independent):
//   rA += Ur*xr ; rB += Ui*xi ; iA += Ur*xi ; iB += Ui*xr
//   yr = rA - rB ; yi = iA + iB
// Gate float4 G[kp*8+q] = (Ur_q, Ui_q, Ur_{q+8}, Ui_{q+8}), Ur=ar, Ui=-ai.

struct Acc2 {
    float rA[2][2], rB[2][2], iA[2][2], iB[2][2];  // [fiber][o], k = q + 8o
};
__device__ __forceinline__ void zero_acc(Acc2& a) {
    #pragma unroll
    for (int f = 0; f < 2; f++)
        #pragma unroll
        for (int o = 0; o < 2; o++) {
            a.rA[f][o] = 0.f; a.rB[f][o] = 0.f;
            a.iA[f][o] = 0.f; a.iB[f][o] = 0.f;
        }
}
__device__ __forceinline__ void mac1(float4 g, float xr, float xi,
                                     Acc2& a, int f) {
    a.rA[f][0] = fmaf(g.x, xr, a.rA[f][0]);
    a.rB[f][0] = fmaf(g.y, xi, a.rB[f][0]);
    a.iA[f][0] = fmaf(g.x, xi, a.iA[f][0]);
    a.iB[f][0] = fmaf(g.y, xr, a.iB[f][0]);
    a.rA[f][1] = fmaf(g.z, xr, a.rA[f][1]);
    a.rB[f][1] = fmaf(g.w, xi, a.rB[f][1]);
    a.iA[f][1] = fmaf(g.z, xi, a.iA[f][1]);
    a.iB[f][1] = fmaf(g.w, xr, a.iB[f][1]);
}
__device__ __forceinline__ float2 fin(const Acc2& a, int f, int o) {
    return make_float2(a.rA[f][o] - a.rB[f][o], a.iA[f][o] + a.iB[f][o]);
}

// ---- contiguous contraction (steps 0, 2): fibers at pb, pb+18 ----
__device__ __forceinline__ void mac_contig(const float2* __restrict__ IN,
                                           const float4* __restrict__ G,
                                           int pb, int q, Acc2& a)
{
    zero_acc(a);
    #pragma unroll
    for (int kp2 = 0; kp2 < 8; kp2++) {
        float4 x0 = *reinterpret_cast<const float4*>(IN + pb + 2 * kp2);
        float4 x1 = *reinterpret_cast<const float4*>(IN + pb + 18 + 2 * kp2);
        #pragma unroll
        for (int sub = 0; sub < 2; sub++) {
            float4 g = G[(2 * kp2 + sub) * 8 + q];
            mac1(g, sub ? x0.z : x0.x, sub ? x0.w : x0.y, a, 0);
            mac1(g, sub ? x1.z : x1.x, sub ? x1.w : x1.y, a, 1);
        }
    }
}

// ---- strided contraction (step 1): fibers adjacent (+1), kp stride 18 ----
__device__ __forceinline__ void mac_strided(const float2* __restrict__ IN,
                                            const float4* __restrict__ G,
                                            int pb, int q, Acc2& a)
{
    zero_acc(a);
    #pragma unroll
    for (int kp = 0; kp < 16; kp++) {
        float4 v = *reinterpret_cast<const float4*>(IN + pb + kp * 18);
        float4 g = G[kp * 8 + q];
        mac1(g, v.x, v.y, a, 0);
        mac1(g, v.z, v.w, a, 1);
    }
}

__global__ __launch_bounds__(1024, 1)
void ulayer_kernel(const float* __restrict__ thetas,
                   const float* __restrict__ evecs,
                   const float* __restrict__ evals,
                   const float* __restrict__ sreal,
                   const float* __restrict__ simag,
                   float* __restrict__ out)
{
    extern __shared__ float2 smem[];
    float2* A   = smem;                 // ping-pong buffers
    float2* Bv  = smem + BUF_F2;
    float2* gs2 = smem + 2 * BUF_F2;    // 3*256 float2 gates

    const int t = threadIdx.x;
    const int b = blockIdx.x;

    // scratch overlay inside Bv (dead until step 0 writes Bv)
    float* Vs = reinterpret_cast<float*>(Bv);   // 16 rows, stride 17
    float* cs = reinterpret_cast<float*>(Bv) + 288;
    float* sn = reinterpret_cast<float*>(Bv) + 336;

    // ---- stage V and sincos ----
    if (t < 256) {
        Vs[(t >> 4) * 17 + (t & 15)] = evecs[t];
    }
    if (t >= 256 && t < 304) {
        int u = t - 256;
        int g = u >> 4, m = u & 15;
        float s, c;
        sincosf(thetas[g] * evals[m], &s, &c);
        cs[g * 16 + m] = c;
        sn[g * 16 + m] = s;
    }
    __syncthreads();

    // ---- build gates: gs2[g*256 + 2*(kp*8 + (k&7)) + (k>>3)] = (Ur, Ui) ----
    if (t < 256) {
        int k = t >> 4, kp = t & 15;
        int slot = 2 * (kp * 8 + (k & 7)) + (k >> 3);
        #pragma unroll
        for (int g = 0; g < 3; g++) {
            float ar = 0.f, ai = 0.f;
            #pragma unroll
            for (int m = 0; m < 16; m++) {
                float p = Vs[k * 17 + m] * Vs[kp * 17 + m];
                ar += p * cs[g * 16 + m];
                ai += p * sn[g * 16 + m];
            }
            gs2[g * 256 + slot] = make_float2(ar, -ai);  // (Ur, Ui)
        }
    }

    // ---- load state into A: LDG.128 + STS.128, 4 elements/thread ----
    {
        const float* srg = sreal + b * DIM;
        const float* sig = simag + b * DIM;
        int i0 = 4 * t;
        float4 r  = *reinterpret_cast<const float4*>(srg + i0);
        float4 im = *reinterpret_cast<const float4*>(sig + i0);
        int p = phys(i0);                 // i0 % 4 == 0 -> no pad crossing
        *reinterpret_cast<float4*>(A + p) =
            make_float4(r.x, im.x, r.y, im.y);
        *reinterpret_cast<float4*>(A + p + 2) =
            make_float4(r.z, im.z, r.w, im.w);
    }
    __syncthreads();

    const float4* g4 = reinterpret_cast<const float4*>(gs2);  // 128 per gate
    const int gg = t >> 3, q = t & 7;   // gg in [0,128), q in [0,8)

    // ======== step 0: U2 contracts c; layout [a][b][kc] ========
    // fibers f = 2gg, 2gg+1 : base phys(32gg) = 36gg + 2*(gg>>3)
    const int pb0 = 36 * gg + 2 * (gg >> 3);
    {
        Acc2 a;
        mac_contig(A, g4 + 2 * 128, pb0, q, a);
        #pragma unroll
        for (int f = 0; f < 2; f++) {
            Bv[pb0 + 18 * f + q]     = fin(a, f, 0);
            Bv[pb0 + 18 * f + q + 8] = fin(a, f, 1);
        }
    }
    __syncthreads();

    // ======== step 1: U1 contracts b; addr = 290*a + 18*b + kc ========
    // fibers (ga, kc), (ga, kc+1) with ga = gg>>3, kc = 2*(gg&7)
    {
        const int ga = gg >> 3, kc = 2 * (gg & 7);
        const int pb = 290 * ga + kc;
        Acc2 a;
        mac_strided(Bv, g4 + 1 * 128, pb, q, a);
        // store to [kb][kc][a]: addr = 290*kb + 18*kc + a
        #pragma unroll
        for (int f = 0; f < 2; f++) {
            int col = 18 * (kc + f) + ga;
            A[290 * q + col]       = fin(a, f, 0);
            A[290 * (q + 8) + col] = fin(a, f, 1);
        }
    }
    __syncthreads();

    // ======== step 2: U0 contracts a; fibers (kb,kc) contiguous ========
    // fibers (kb, kc), (kb, kc+1): base = 290*kb + 18*kc
    {
        const int kb = gg >> 3, kc = 2 * (gg & 7);
        const int pb = 290 * kb + 18 * kc;
        Acc2 a;
        mac_contig(A, g4 + 0 * 128, pb, q, a);
        float* outr = out + b * DIM;
        float* outi = out + (size_t)BATCH * DIM + b * DIM;
        #pragma unroll
        for (int o = 0; o < 2; o++) {
            int ka = q + 8 * o;
            float2 y0 = fin(a, 0, o);
            float2 y1 = fin(a, 1, o);
            int d = ka * 256 + kb * 16 + kc;
            *reinterpret_cast<float2*>(outr + d) = make_float2(y0.x, y1.x);
            *reinterpret_cast<float2*>(outi + d) = make_float2(y0.y, y1.y);
        }
    }
}

extern "C" void kernel_launch(void* const* d_in, const int* in_sizes, int n_in,
                              void* d_out, int out_size) {
    const float* thetas = (const float*)d_in[0];
    const float* evecs  = (const float*)d_in[1];
    const float* evals  = (const float*)d_in[2];
    const float* sreal  = (const float*)d_in[3];
    const float* simag  = (const float*)d_in[4];

    const int smem_bytes = 2 * BUF_F2 * sizeof(float2) + 3 * 256 * sizeof(float2);
    static bool attr_set = false;
    if (!attr_set) {
        cudaFuncSetAttribute(ulayer_kernel,
                             cudaFuncAttributeMaxDynamicSharedMemorySize,
                             smem_bytes);
        attr_set = true;
    }
    ulayer_kernel<<<BATCH, 1024, smem_bytes>>>(thetas, evecs, evals,
                                               sreal, simag, (float*)d_out);
}

// round 14
// speedup vs baseline: 1.0205x; 1.0205x over previous
#include <cuda_runtime.h>

#define BATCH 128
#define DIM   4096

// ---- smem plan (float2 units) ----
// tileA: [0, 4608)       16 warps x (16 rows x 18)   input slices
// tileB: [4608, 9216)    16 warps x (16 rows x 18)   step-0 output
// Bbuf:  [9216, 13856)   kb*290 + kc*18 + a  (4640)  step-1 output
// gates: [13856, 14624)  3 x 256 float2, read as float4 pairs
#define TA_OFF 0
#define TB_OFF 4608
#define BB_OFF 9216
#define GS_OFF 13856
#define SMEM_F2 14624

// Scalar complex MAC with SPLIT accumulators (all FMAs independent):
//   rA += Ur*xr ; rB += Ui*xi ; iA += Ur*xi ; iB += Ui*xr
//   yr = rA - rB ; yi = iA + iB
// Gate float4 G[kp*8+q] = (Ur_q, Ui_q, Ur_{q+8}, Ui_{q+8}), Ur=ar, Ui=-ai.

struct AccS {
    float rA[4][2], rB[4][2], iA[4][2], iB[4][2];  // [fiber][o], k = q + 8o
};
__device__ __forceinline__ void zero_acc(AccS& a) {
    #pragma unroll
    for (int f = 0; f < 4; f++)
        #pragma unroll
        for (int o = 0; o < 2; o++) {
            a.rA[f][o] = 0.f; a.rB[f][o] = 0.f;
            a.iA[f][o] = 0.f; a.iB[f][o] = 0.f;
        }
}
__device__ __forceinline__ void mac1(float4 g, float xr, float xi,
                                     AccS& a, int f) {
    a.rA[f][0] = fmaf(g.x, xr, a.rA[f][0]);
    a.rB[f][0] = fmaf(g.y, xi, a.rB[f][0]);
    a.iA[f][0] = fmaf(g.x, xi, a.iA[f][0]);
    a.iB[f][0] = fmaf(g.y, xr, a.iB[f][0]);
    a.rA[f][1] = fmaf(g.z, xr, a.rA[f][1]);
    a.rB[f][1] = fmaf(g.w, xi, a.rB[f][1]);
    a.iA[f][1] = fmaf(g.z, xi, a.iA[f][1]);
    a.iB[f][1] = fmaf(g.w, xr, a.iB[f][1]);
}
__device__ __forceinline__ float2 fin(const AccS& a, int f, int o) {
    return make_float2(a.rA[f][o] - a.rB[f][o], a.iA[f][o] + a.iB[f][o]);
}

// 16x16 contraction over 4 fibers at IN + ff*RS, contracted index contiguous.
template<int RS>
__device__ __forceinline__ void mac_tile(const float2* __restrict__ IN,
                                         const float4* __restrict__ G,
                                         int q, AccS& a)
{
    zero_acc(a);
    #pragma unroll
    for (int kp2 = 0; kp2 < 8; kp2++) {
        float4 xv[4];
        #pragma unroll
        for (int ff = 0; ff < 4; ff++)
            xv[ff] = *reinterpret_cast<const float4*>(IN + ff * RS + 2 * kp2);
        #pragma unroll
        for (int sub = 0; sub < 2; sub++) {
            float4 g = G[(2 * kp2 + sub) * 8 + q];
            #pragma unroll
            for (int ff = 0; ff < 4; ff++)
                mac1(g, sub ? xv[ff].z : xv[ff].x,
                        sub ? xv[ff].w : xv[ff].y, a, ff);
        }
    }
}

__global__ __launch_bounds__(512, 1)
void ulayer_kernel(const float* __restrict__ thetas,
                   const float* __restrict__ evecs,
                   const float* __restrict__ evals,
                   const float* __restrict__ sreal,
                   const float* __restrict__ simag,
                   float* __restrict__ out)
{
    extern __shared__ float2 smem[];
    float2* tA  = smem + TA_OFF;
    float2* tB  = smem + TB_OFF;
    float2* Bb  = smem + BB_OFF;
    float2* gs2 = smem + GS_OFF;

    const int t = threadIdx.x;
    const int b0 = blockIdx.x;
    const int w = t >> 5, l = t & 31;

    // ---- each warp loads its own a-slice (a = w) into tileA ----
    {
        const float* srg = sreal + b0 * DIM + w * 256 + l * 8;
        const float* sig = simag + b0 * DIM + w * 256 + l * 8;
        float4 r0 = *reinterpret_cast<const float4*>(srg);
        float4 r1 = *reinterpret_cast<const float4*>(srg + 4);
        float4 i0 = *reinterpret_cast<const float4*>(sig);
        float4 i1 = *reinterpret_cast<const float4*>(sig + 4);
        int row = l >> 1, c0 = (l & 1) * 8;
        float2* dst = tA + w * 288 + row * 18 + c0;
        *reinterpret_cast<float4*>(dst + 0) = make_float4(r0.x, i0.x, r0.y, i0.y);
        *reinterpret_cast<float4*>(dst + 2) = make_float4(r0.z, i0.z, r0.w, i0.w);
        *reinterpret_cast<float4*>(dst + 4) = make_float4(r1.x, i1.x, r1.y, i1.y);
        *reinterpret_cast<float4*>(dst + 6) = make_float4(r1.z, i1.z, r1.w, i1.w);
    }

    // scratch overlay inside Bbuf (dead until step 1 writes it)
    float* Vs = reinterpret_cast<float*>(Bb);   // 16 rows, stride 17
    float* cs = Vs + 288;
    float* sn = Vs + 336;

    // ---- stage V and sincos ----
    if (t < 256) {
        Vs[(t >> 4) * 17 + (t & 15)] = evecs[t];
    }
    if (t >= 256 && t < 304) {
        int u = t - 256;
        int g = u >> 4, m = u & 15;
        float s, c;
        sincosf(thetas[g] * evals[m], &s, &c);
        cs[g * 16 + m] = c;
        sn[g * 16 + m] = s;
    }
    __syncthreads();

    // ---- build gates: gs2[g*256 + 2*(kp*8 + (k&7)) + (k>>3)] = (Ur, Ui) ----
    if (t < 256) {
        int k = t >> 4, kp = t & 15;
        int slot = 2 * (kp * 8 + (k & 7)) + (k >> 3);
        #pragma unroll
        for (int g = 0; g < 3; g++) {
            float ar = 0.f, ai = 0.f;
            #pragma unroll
            for (int m = 0; m < 16; m++) {
                float p = Vs[k * 17 + m] * Vs[kp * 17 + m];
                ar += p * cs[g * 16 + m];
                ai += p * sn[g * 16 + m];
            }
            gs2[g * 256 + slot] = make_float2(ar, -ai);  // (Ur, Ui)
        }
    }
    __syncthreads();   // gates + all tiles ready

    const float4* g4 = reinterpret_cast<const float4*>(gs2);  // 128/gate
    const int f2 = l >> 3, q = l & 7;   // f2 in [0,4), q in [0,8)

    // ======== step 0 (warp-local): U2 contracts c; tile[b][c] ========
    {
        AccS a;
        mac_tile<18>(tA + w * 288 + f2 * 72, g4 + 2 * 128, q, a);
        float2* ob = tB + w * 288;
        #pragma unroll
        for (int ff = 0; ff < 4; ff++) {
            int bb = 4 * f2 + ff;
            ob[q * 18 + bb]       = fin(a, ff, 0);   // tB[kc][b]
            ob[(q + 8) * 18 + bb] = fin(a, ff, 1);
        }
    }
    __syncwarp();

    // ======== step 1 (warp-local): U1 contracts b; tile[kc][b] ========
    {
        AccS a;
        mac_tile<18>(tB + w * 288 + f2 * 72, g4 + 1 * 128, q, a);
        // store y[kb][kc] for a=w: Bb[kb*290 + kc*18 + a]
        #pragma unroll
        for (int ff = 0; ff < 4; ff++) {
            int kc = 4 * f2 + ff;
            Bb[q * 290 + kc * 18 + w]       = fin(a, ff, 0);
            Bb[(q + 8) * 290 + kc * 18 + w] = fin(a, ff, 1);
        }
    }
    __syncthreads();   // the ONE cross-warp barrier

    // ======== step 2: U0 contracts a; fibers (kb,kc), a contiguous ========
    {
        const int gg = t >> 3;              // 0..63 ; kb = gg>>2, kc0 = 4*(gg&3)
        const int kb = gg >> 2, kc0 = 4 * (gg & 3);
        AccS a;
        mac_tile<18>(Bb + kb * 290 + kc0 * 18, g4 + 0 * 128, q, a);
        float* outr = out + b0 * DIM;
        float* outi = out + (size_t)BATCH * DIM + b0 * DIM;
        const int r0 = 4 * gg;              // = kb*16 + kc0
        #pragma unroll
        for (int o = 0; o < 2; o++) {
            int ka = q + 8 * o;
            float2 y0 = fin(a, 0, o);
            float2 y1 = fin(a, 1, o);
            float2 y2 = fin(a, 2, o);
            float2 y3 = fin(a, 3, o);
            *reinterpret_cast<float4*>(outr + ka * 256 + r0) =
                make_float4(y0.x, y1.x, y2.x, y3.x);
            *reinterpret_cast<float4*>(outi + ka * 256 + r0) =
                make_float4(y0.y, y1.y, y2.y, y3.y);
        }
    }
}

extern "C" void kernel_launch(void* const* d_in, const int* in_sizes, int n_in,
                              void* d_out, int out_size) {
    const float* thetas = (const float*)d_in[0];
    const float* evecs  = (const float*)d_in[1];
    const float* evals  = (const float*)d_in[2];
    const float* sreal  = (const float*)d_in[3];
    const float* simag  = (const float*)d_in[4];

    const int smem_bytes = SMEM_F2 * sizeof(float2);   // 116,992 B
    static bool attr_set = false;
    if (!attr_set) {
        cudaFuncSetAttribute(ulayer_kernel,
                             cudaFuncAttributeMaxDynamicSharedMemorySize,
                             smem_bytes);
        attr_set = true;
    }
    ulayer_kernel<<<BATCH, 512, smem_bytes>>>(thetas, evecs, evals,
                                              sreal, simag, (float*)d_out);
}